// round 14
// baseline (speedup 1.0000x reference)
#include <cuda_runtime.h>

#define N_QUBITS 7
#define DIM 128
#define DEPTH 2
#define NTHETA 14

typedef unsigned long long u64;

__device__ __forceinline__ u64 fma2(u64 a, u64 b, u64 c) {
    u64 d; asm("fma.rn.f32x2 %0, %1, %2, %3;" : "=l"(d) : "l"(a), "l"(b), "l"(c)); return d;
}
__device__ __forceinline__ u64 mul2(u64 a, u64 b) {
    u64 d; asm("mul.rn.f32x2 %0, %1, %2;" : "=l"(d) : "l"(a), "l"(b)); return d;
}
__device__ __forceinline__ u64 add2(u64 a, u64 b) {
    u64 d; asm("add.rn.f32x2 %0, %1, %2;" : "=l"(d) : "l"(a), "l"(b)); return d;
}
__device__ __forceinline__ u64 pack2(float lo, float hi) {
    u64 d; asm("mov.b64 %0, {%1, %2};" : "=l"(d) : "f"(lo), "f"(hi)); return d;
}

// R11 transform (best measured: thread-per-row, v[64], no cross-lane ops in
// the transform) + DOUBLE-BUFFERED loads: each warp owns 64 rows as two
// 32-row batches with separate cp.async commit groups. Batch B streams in
// while batch A computes, halving exposed DRAM waits per row (R11 limiter:
// issue 45.8%, one serial wait per batch). Non-persistent 32-thread blocks
// keep the churn-based phase diversity (R6 lesson: persistent convoys stall).
//
// Proven elements: cp.async issued FIRST, __tanf prep hidden behind loads,
// coefficients register-broadcast, depth loop fully unrolled (R10 LDL lesson).
//
// State: v[j] = (amp[2j], amp[2j+1]) packed f32x2, j = 0..63.
// Qubit q>=1 maps to bit (q-1) of j; qubit 0 is the lo/hi split.
// Tangent form: (A,B) -> (A - t*B, B + t*A); global prod(cos) cancels in
// out = num / sum(probs).
__global__ void __launch_bounds__(32, 7)
qnat_main_kernel(const float* __restrict__ embed,
                 const float* __restrict__ theta,
                 float* __restrict__ out,
                 int nrows) {
    extern __shared__ ulonglong2 buf[];   // [2][32][32]: 2 batches x 32 rows x 32 chunks

    const int l = threadIdx.x;
    const long long rowbase = (long long)blockIdx.x * 64;
    if (rowbase >= nrows) return;

    // ---- 1) issue BOTH batch fetches up front (2 commit groups) ----
    #pragma unroll
    for (int h = 0; h < 2; h++) {
        const long long rb = rowbase + h * 32;
        const int vld = (int)(((long long)nrows - rb) < 32
                              ? (nrows - rb < 0 ? 0 : nrows - rb) : 32);
        const float4* src = reinterpret_cast<const float4*>(embed + rb * DIM);
        #pragma unroll
        for (int it = 0; it < 32; it++) {
            if (it < vld) {
                unsigned dst = (unsigned)__cvta_generic_to_shared(
                    &buf[(h * 32 + it) * 32 + (l ^ it)]);
                asm volatile("cp.async.cg.shared.global [%0], [%1], 16;"
                             :: "r"(dst), "l"(src + it * 32 + l) : "memory");
            }
        }
        asm volatile("cp.async.commit_group;" ::: "memory");
    }

    // ---- 2) coefficients -> registers, hidden behind the in-flight loads ----
    float tv = 0.0f;
    if (l < NTHETA) tv = __tanf(theta[l] * 0.5f);
    float tn[NTHETA];
    #pragma unroll
    for (int i = 0; i < NTHETA; i++)
        tn[i] = __shfl_sync(0xffffffffu, tv, i);

    // ---- 3) process the two batches back to back ----
    #pragma unroll
    for (int h = 0; h < 2; h++) {
        if (h == 0)
            asm volatile("cp.async.wait_group 1;" ::: "memory");  // A ready, B in flight
        else
            asm volatile("cp.async.wait_group 0;" ::: "memory");  // B ready (mostly free)
        __syncwarp();

        const long long rb = rowbase + h * 32;
        if (rb + l >= nrows) continue;   // tail guard (no cross-lane ops below)

        // ---- own row into packed registers (conflict-free swizzled LDS.128) ----
        u64 v[64];
        #pragma unroll
        for (int i = 0; i < 32; i++) {
            ulonglong2 g = buf[(h * 32 + l) * 32 + (i ^ l)];
            v[2 * i]     = g.x;   // (amp 4i,   amp 4i+1)
            v[2 * i + 1] = g.y;   // (amp 4i+2, amp 4i+3)
        }

        // ---- 2 depths of 7 tangent-form RY rotations + CZ between ----
        #pragma unroll
        for (int d = 0; d < DEPTH; d++) {
            const int t0 = d * N_QUBITS;
            // qubit 0 (lo/hi split): v' = v + (-t,+t)*(hi,lo)
            {
                float t = tn[t0];
                u64 np = pack2(-t, t);
                #pragma unroll
                for (int j = 0; j < 64; j++) {
                    u64 sw = (v[j] << 32) | (v[j] >> 32);
                    v[j] = fma2(np, sw, v[j]);
                }
            }
            // qubits 1..6: A' = A - t*B ; B' = B + t*A
            #pragma unroll
            for (int q = 1; q < N_QUBITS; q++) {
                float t = tn[t0 + q];
                u64 tt = pack2(t, t);
                u64 nt = pack2(-t, -t);
                const int m = 1 << (q - 1);
                #pragma unroll
                for (int j = 0; j < 64; j++) {
                    if (!(j & m)) {
                        u64 A = v[j];
                        v[j]     = fma2(nt, v[j + m], A);
                        v[j + m] = fma2(tt, A, v[j + m]);
                    }
                }
            }
            // CZ after depth 0 only (final CZ erased by squaring): sign masks
            if (d == 0) {
                #pragma unroll
                for (int j = 0; j < 64; j++) {
                    int tb = j & (j >> 1);
                    int pj = (tb ^ (tb >> 1) ^ (tb >> 2) ^ (tb >> 3) ^ (tb >> 4)) & 1;
                    int ph = pj ^ (j & 1);
                    u64 mask = (pj ? 0x80000000ull : 0ull) |
                               (ph ? 0x8000000000000000ull : 0ull);
                    if (mask) v[j] ^= mask;
                }
            }
        }

        // ---- probabilities (packed squares) ----
        #pragma unroll
        for (int j = 0; j < 64; j++) v[j] = mul2(v[j], v[j]);

        // ---- in-place packed subset-sum tree over the 6 bits of j ----
        #pragma unroll
        for (int k = 0; k < 6; k++) {
            const int m = 1 << k;
            #pragma unroll
            for (int base = 0; base < 64; base += 2 * m) {
                v[base] = add2(v[base], v[base + m]);
                #pragma unroll
                for (int t = 0; t < k; t++)
                    v[base + (1 << t)] = add2(v[base + (1 << t)], v[base + m + (1 << t)]);
            }
        }

        // ---- finalize: S, z0 from lo/hi split; z1..z6 from subset sums ----
        float lo = __uint_as_float((unsigned)v[0]);
        float hi = __uint_as_float((unsigned)(v[0] >> 32));
        float S   = lo + hi;
        float z0  = lo - hi;
        float inv = __fdividef(1.0f, S);

        float* o = out + (rb + l) * N_QUBITS;
        o[0] = z0 * inv;
        #pragma unroll
        for (int q = 1; q < N_QUBITS; q++) {
            u64 G = v[1 << (q - 1)];
            float gs = __uint_as_float((unsigned)G) +
                       __uint_as_float((unsigned)(G >> 32));
            o[q] = fmaf(-2.0f * gs, inv, 1.0f);   // (S - 2*gs)/S
        }
    }
}

extern "C" void kernel_launch(void* const* d_in, const int* in_sizes, int n_in,
                              void* d_out, int out_size) {
    const float* embed = (const float*)d_in[0];
    const float* theta = (const float*)d_in[1];
    float* out = (float*)d_out;

    const int smem_bytes = 2 * 32 * 32 * sizeof(ulonglong2);   // 32 KB

    static bool attr_set = false;
    if (!attr_set) {
        cudaFuncSetAttribute(qnat_main_kernel,
                             cudaFuncAttributePreferredSharedMemoryCarveout, 100);
        cudaFuncSetAttribute(qnat_main_kernel,
                             cudaFuncAttributeMaxDynamicSharedMemorySize, smem_bytes);
        attr_set = true;
    }

    int nrows = in_sizes[0] / DIM;
    int grid = (nrows + 63) / 64;    // 64 rows per 32-thread block

    qnat_main_kernel<<<grid, 32, smem_bytes>>>(embed, theta, out, nrows);
}

// round 15
// speedup vs baseline: 1.3268x; 1.3268x over previous
#include <cuda_runtime.h>

#define N_QUBITS 7
#define DIM 128
#define DEPTH 2
#define NTHETA 14

typedef unsigned long long u64;

__device__ __forceinline__ u64 fma2(u64 a, u64 b, u64 c) {
    u64 d; asm("fma.rn.f32x2 %0, %1, %2, %3;" : "=l"(d) : "l"(a), "l"(b), "l"(c)); return d;
}
__device__ __forceinline__ u64 mul2(u64 a, u64 b) {
    u64 d; asm("mul.rn.f32x2 %0, %1, %2;" : "=l"(d) : "l"(a), "l"(b)); return d;
}
__device__ __forceinline__ u64 add2(u64 a, u64 b) {
    u64 d; asm("add.rn.f32x2 %0, %1, %2;" : "=l"(d) : "l"(a), "l"(b)); return d;
}
__device__ __forceinline__ u64 pack2(float lo, float hi) {
    u64 d; asm("mov.b64 %0, {%1, %2};" : "=l"(d) : "f"(lo), "f"(hi)); return d;
}

// R11 body (proven best: thread-per-row, v[64], tangent-form, no cross-lane
// ops in the transform) reshaped to 3 warps / 96 threads per block so the SM
// reaches its REGFILE occupancy ceiling:
//   158 regs/thread -> floor(64K/5056) = 12 warps/SM;
//   2-warp blocks quantize to 5 CTAs = 10 warps (R11);
//   3-warp blocks with 48KB tiles give 4 CTAs x 3 = 12 warps (+20%).
// R14 lesson: resident-warp count beats per-warp double buffering — keep one
// batch per warp, non-persistent, block-churn phase diversity.
//
// State: v[j] = (amp[2j], amp[2j+1]) packed f32x2, j = 0..63.
// Qubit q>=1 maps to bit (q-1) of j; qubit 0 is the lo/hi split.
// Tangent form: (A,B) -> (A - t*B, B + t*A); global prod(cos) cancels in
// out = num / sum(probs).
__global__ void __launch_bounds__(96, 4)
qnat_main_kernel(const float* __restrict__ embed,
                 const float* __restrict__ theta,
                 float* __restrict__ out,
                 int nrows) {
    extern __shared__ ulonglong2 buf[];   // [3][32][32] 16B chunks, XOR-swizzled

    const int l = threadIdx.x & 31;
    const int w = threadIdx.x >> 5;

    const long long rowbase = ((long long)blockIdx.x * 3 + w) * 32;
    if (rowbase >= nrows) return;   // whole-warp uniform exit
    const int valid = (int)(((long long)nrows - rowbase) < 32 ? (nrows - rowbase) : 32);

    // ---- 1) issue the DRAM fetch first (coalesced cp.async, XOR-16B swizzle) ----
    const float4* src = reinterpret_cast<const float4*>(embed + rowbase * DIM);
    #pragma unroll
    for (int it = 0; it < 32; it++) {
        if (it < valid) {
            unsigned dst = (unsigned)__cvta_generic_to_shared(
                &buf[(w * 32 + it) * 32 + (l ^ it)]);
            asm volatile("cp.async.cg.shared.global [%0], [%1], 16;"
                         :: "r"(dst), "l"(src + it * 32 + l) : "memory");
        }
    }
    asm volatile("cp.async.commit_group;" ::: "memory");

    // ---- 2) coefficients -> registers, hidden behind the in-flight loads ----
    float tv = 0.0f;
    if (l < NTHETA) tv = __tanf(theta[l] * 0.5f);
    float tn[NTHETA];
    #pragma unroll
    for (int i = 0; i < NTHETA; i++)
        tn[i] = __shfl_sync(0xffffffffu, tv, i);

    // ---- 3) wait for data ----
    asm volatile("cp.async.wait_group 0;" ::: "memory");
    __syncwarp();
    if (l >= valid) return;

    // ---- own row into packed registers (conflict-free swizzled LDS.128) ----
    u64 v[64];
    #pragma unroll
    for (int i = 0; i < 32; i++) {
        ulonglong2 g = buf[(w * 32 + l) * 32 + (i ^ l)];
        v[2 * i]     = g.x;   // (amp 4i,   amp 4i+1)
        v[2 * i + 1] = g.y;   // (amp 4i+2, amp 4i+3)
    }

    // ---- 2 depths of 7 tangent-form RY rotations + CZ between ----
    // FULLY unrolled: all tn[] indices are compile-time constants (R10 lesson).
    #pragma unroll
    for (int d = 0; d < DEPTH; d++) {
        const int t0 = d * N_QUBITS;
        // qubit 0 (lo/hi split): v' = v + (-t,+t)*(hi,lo)
        {
            float t = tn[t0];
            u64 np = pack2(-t, t);
            #pragma unroll
            for (int j = 0; j < 64; j++) {
                u64 sw = (v[j] << 32) | (v[j] >> 32);
                v[j] = fma2(np, sw, v[j]);
            }
        }
        // qubits 1..6: A' = A - t*B ; B' = B + t*A
        #pragma unroll
        for (int q = 1; q < N_QUBITS; q++) {
            float t = tn[t0 + q];
            u64 tt = pack2(t, t);
            u64 nt = pack2(-t, -t);
            const int m = 1 << (q - 1);
            #pragma unroll
            for (int j = 0; j < 64; j++) {
                if (!(j & m)) {
                    u64 A = v[j];
                    v[j]     = fma2(nt, v[j + m], A);
                    v[j + m] = fma2(tt, A, v[j + m]);
                }
            }
        }
        // CZ after depth 0 only (final CZ erased by squaring): sign-bit masks
        if (d == 0) {
            #pragma unroll
            for (int j = 0; j < 64; j++) {
                int tb = j & (j >> 1);
                int pj = (tb ^ (tb >> 1) ^ (tb >> 2) ^ (tb >> 3) ^ (tb >> 4)) & 1;
                int ph = pj ^ (j & 1);
                u64 mask = (pj ? 0x80000000ull : 0ull) |
                           (ph ? 0x8000000000000000ull : 0ull);
                if (mask) v[j] ^= mask;
            }
        }
    }

    // ---- probabilities (packed squares) ----
    #pragma unroll
    for (int j = 0; j < 64; j++) v[j] = mul2(v[j], v[j]);

    // ---- in-place packed subset-sum tree over the 6 bits of j ----
    // invariant per block @base size 2^k: v[base]=total, v[base+2^t]=sum{bit_t=1}
    #pragma unroll
    for (int k = 0; k < 6; k++) {
        const int m = 1 << k;
        #pragma unroll
        for (int base = 0; base < 64; base += 2 * m) {
            v[base] = add2(v[base], v[base + m]);
            #pragma unroll
            for (int t = 0; t < k; t++)
                v[base + (1 << t)] = add2(v[base + (1 << t)], v[base + m + (1 << t)]);
        }
    }

    // ---- finalize: S, z0 from lo/hi split; z1..z6 from subset sums ----
    float lo = __uint_as_float((unsigned)v[0]);
    float hi = __uint_as_float((unsigned)(v[0] >> 32));
    float S   = lo + hi;
    float z0  = lo - hi;
    float inv = __fdividef(1.0f, S);

    float* o = out + (rowbase + l) * N_QUBITS;
    o[0] = z0 * inv;
    #pragma unroll
    for (int q = 1; q < N_QUBITS; q++) {
        u64 G = v[1 << (q - 1)];
        float gs = __uint_as_float((unsigned)G) + __uint_as_float((unsigned)(G >> 32));
        o[q] = fmaf(-2.0f * gs, inv, 1.0f);   // (S - 2*gs)/S
    }
}

extern "C" void kernel_launch(void* const* d_in, const int* in_sizes, int n_in,
                              void* d_out, int out_size) {
    const float* embed = (const float*)d_in[0];
    const float* theta = (const float*)d_in[1];
    float* out = (float*)d_out;

    const int smem_bytes = 3 * 32 * 32 * sizeof(ulonglong2);   // 48 KB

    static bool attr_set = false;
    if (!attr_set) {
        cudaFuncSetAttribute(qnat_main_kernel,
                             cudaFuncAttributePreferredSharedMemoryCarveout, 100);
        cudaFuncSetAttribute(qnat_main_kernel,
                             cudaFuncAttributeMaxDynamicSharedMemorySize, smem_bytes);
        attr_set = true;
    }

    int nrows = in_sizes[0] / DIM;
    int nbatches = (nrows + 31) / 32;      // 32 rows per warp
    int grid = (nbatches + 2) / 3;         // 3 warps (96 threads) per block

    qnat_main_kernel<<<grid, 96, smem_bytes>>>(embed, theta, out, nrows);
}

// round 16
// speedup vs baseline: 1.4215x; 1.0714x over previous
#include <cuda_runtime.h>

#define N_QUBITS 7
#define DIM 128
#define DEPTH 2
#define NTHETA 14

typedef unsigned long long u64;

__device__ __forceinline__ u64 fma2(u64 a, u64 b, u64 c) {
    u64 d; asm("fma.rn.f32x2 %0, %1, %2, %3;" : "=l"(d) : "l"(a), "l"(b), "l"(c)); return d;
}
__device__ __forceinline__ u64 mul2(u64 a, u64 b) {
    u64 d; asm("mul.rn.f32x2 %0, %1, %2;" : "=l"(d) : "l"(a), "l"(b)); return d;
}
__device__ __forceinline__ u64 add2(u64 a, u64 b) {
    u64 d; asm("add.rn.f32x2 %0, %1, %2;" : "=l"(d) : "l"(a), "l"(b)); return d;
}
__device__ __forceinline__ u64 pack2(float lo, float hi) {
    u64 d; asm("mov.b64 %0, {%1, %2};" : "=l"(d) : "f"(lo), "f"(hi)); return d;
}

// R11/R15 structure (proven best: thread-per-row, v[64] packed f32x2,
// tangent-form rotations, cp.async-first, register coefficients, fully
// unrolled) with two changes:
//  1. Qubit-0 rotation on SCALAR HALVES: lo' = fma(-t,hi,lo), hi' = fma(t,lo,hi).
//     The packed form needed a materialized swapped register pair (~2 ALU/elem)
//     before each fma2 — ~256 ALU slots/thread total. Scalar halves are free
//     register naming; net issue-slot cut ~8-10% (alu 27% was the target).
//  2. 4-warp / 128-thread blocks, 64KB dynamic smem: 3 CTAs x 4 = 12 warps/SM
//     theoretical (regs 156*128*3 = 59.9k < 64K; smem 192KB < 228KB).
__global__ void __launch_bounds__(128, 3)
qnat_main_kernel(const float* __restrict__ embed,
                 const float* __restrict__ theta,
                 float* __restrict__ out,
                 int nrows) {
    extern __shared__ ulonglong2 buf[];   // [4][32][32] 16B chunks, XOR-swizzled

    const int l = threadIdx.x & 31;
    const int w = threadIdx.x >> 5;

    const long long rowbase = ((long long)blockIdx.x * 4 + w) * 32;
    if (rowbase >= nrows) return;   // whole-warp uniform exit
    const int valid = (int)(((long long)nrows - rowbase) < 32 ? (nrows - rowbase) : 32);

    // ---- 1) issue the DRAM fetch first (coalesced cp.async, XOR-16B swizzle) ----
    const float4* src = reinterpret_cast<const float4*>(embed + rowbase * DIM);
    #pragma unroll
    for (int it = 0; it < 32; it++) {
        if (it < valid) {
            unsigned dst = (unsigned)__cvta_generic_to_shared(
                &buf[(w * 32 + it) * 32 + (l ^ it)]);
            asm volatile("cp.async.cg.shared.global [%0], [%1], 16;"
                         :: "r"(dst), "l"(src + it * 32 + l) : "memory");
        }
    }
    asm volatile("cp.async.commit_group;" ::: "memory");

    // ---- 2) coefficients -> registers, hidden behind the in-flight loads ----
    float tv = 0.0f;
    if (l < NTHETA) tv = __tanf(theta[l] * 0.5f);
    float tn[NTHETA];
    #pragma unroll
    for (int i = 0; i < NTHETA; i++)
        tn[i] = __shfl_sync(0xffffffffu, tv, i);

    // ---- 3) wait for data ----
    asm volatile("cp.async.wait_group 0;" ::: "memory");
    __syncwarp();
    if (l >= valid) return;

    // ---- own row into packed registers (conflict-free swizzled LDS.128) ----
    u64 v[64];
    #pragma unroll
    for (int i = 0; i < 32; i++) {
        ulonglong2 g = buf[(w * 32 + l) * 32 + (i ^ l)];
        v[2 * i]     = g.x;   // (amp 4i,   amp 4i+1)
        v[2 * i + 1] = g.y;   // (amp 4i+2, amp 4i+3)
    }

    // ---- 2 depths of 7 tangent-form RY rotations + CZ between ----
    // FULLY unrolled: all tn[] indices are compile-time constants (R10 lesson).
    #pragma unroll
    for (int d = 0; d < DEPTH; d++) {
        const int t0 = d * N_QUBITS;
        // qubit 0 on scalar halves (no packed swap materialization)
        {
            float t = tn[t0];
            #pragma unroll
            for (int j = 0; j < 64; j++) {
                float flo = __uint_as_float((unsigned)v[j]);
                float fhi = __uint_as_float((unsigned)(v[j] >> 32));
                float nlo = fmaf(-t, fhi, flo);
                float nhi = fmaf( t, flo, fhi);
                v[j] = pack2(nlo, nhi);
            }
        }
        // qubits 1..6: A' = A - t*B ; B' = B + t*A  (packed, 2 fma2 / 4 amps)
        #pragma unroll
        for (int q = 1; q < N_QUBITS; q++) {
            float t = tn[t0 + q];
            u64 tt = pack2(t, t);
            u64 nt = pack2(-t, -t);
            const int m = 1 << (q - 1);
            #pragma unroll
            for (int j = 0; j < 64; j++) {
                if (!(j & m)) {
                    u64 A = v[j];
                    v[j]     = fma2(nt, v[j + m], A);
                    v[j + m] = fma2(tt, A, v[j + m]);
                }
            }
        }
        // CZ after depth 0 only (final CZ erased by squaring): sign-bit masks
        if (d == 0) {
            #pragma unroll
            for (int j = 0; j < 64; j++) {
                int tb = j & (j >> 1);
                int pj = (tb ^ (tb >> 1) ^ (tb >> 2) ^ (tb >> 3) ^ (tb >> 4)) & 1;
                int ph = pj ^ (j & 1);
                u64 mask = (pj ? 0x80000000ull : 0ull) |
                           (ph ? 0x8000000000000000ull : 0ull);
                if (mask) v[j] ^= mask;
            }
        }
    }

    // ---- probabilities (packed squares) ----
    #pragma unroll
    for (int j = 0; j < 64; j++) v[j] = mul2(v[j], v[j]);

    // ---- in-place packed subset-sum tree over the 6 bits of j ----
    // invariant per block @base size 2^k: v[base]=total, v[base+2^t]=sum{bit_t=1}
    #pragma unroll
    for (int k = 0; k < 6; k++) {
        const int m = 1 << k;
        #pragma unroll
        for (int base = 0; base < 64; base += 2 * m) {
            v[base] = add2(v[base], v[base + m]);
            #pragma unroll
            for (int t = 0; t < k; t++)
                v[base + (1 << t)] = add2(v[base + (1 << t)], v[base + m + (1 << t)]);
        }
    }

    // ---- finalize: S, z0 from lo/hi split; z1..z6 from subset sums ----
    float lo = __uint_as_float((unsigned)v[0]);
    float hi = __uint_as_float((unsigned)(v[0] >> 32));
    float S   = lo + hi;
    float z0  = lo - hi;
    float inv = __fdividef(1.0f, S);

    float* o = out + (rowbase + l) * N_QUBITS;
    o[0] = z0 * inv;
    #pragma unroll
    for (int q = 1; q < N_QUBITS; q++) {
        u64 G = v[1 << (q - 1)];
        float gs = __uint_as_float((unsigned)G) + __uint_as_float((unsigned)(G >> 32));
        o[q] = fmaf(-2.0f * gs, inv, 1.0f);   // (S - 2*gs)/S
    }
}

extern "C" void kernel_launch(void* const* d_in, const int* in_sizes, int n_in,
                              void* d_out, int out_size) {
    const float* embed = (const float*)d_in[0];
    const float* theta = (const float*)d_in[1];
    float* out = (float*)d_out;

    const int smem_bytes = 4 * 32 * 32 * sizeof(ulonglong2);   // 64 KB

    static bool attr_set = false;
    if (!attr_set) {
        cudaFuncSetAttribute(qnat_main_kernel,
                             cudaFuncAttributePreferredSharedMemoryCarveout, 100);
        cudaFuncSetAttribute(qnat_main_kernel,
                             cudaFuncAttributeMaxDynamicSharedMemorySize, smem_bytes);
        attr_set = true;
    }

    int nrows = in_sizes[0] / DIM;
    int nbatches = (nrows + 31) / 32;      // 32 rows per warp
    int grid = (nbatches + 3) / 4;         // 4 warps (128 threads) per block

    qnat_main_kernel<<<grid, 128, smem_bytes>>>(embed, theta, out, nrows);
}